// round 5
// baseline (speedup 1.0000x reference)
#include <cuda_runtime.h>
#include <cuda_bf16.h>
#include <cstdint>
#include <math.h>

#define Bsz 32
#define Nn  1024
#define Dd  128
#define NROWS (Bsz*Nn)

// Scratch (device globals: allocation-free rule)
__device__ float g_itr[NROWS * Dd];          // itr_attn fp32
__device__ float g_qa[NROWS];                // qa[j] = P[j].wa
__device__ uint32_t g_whu[3 * 16384];        // weights bf16x2 hi (3 x 256x128)
__device__ uint32_t g_wlu[3 * 16384];        // weights bf16x2 lo

// ===========================================================================
// helpers
// ===========================================================================
__device__ __forceinline__ uint32_t smem_u32(const void* p) {
    uint32_t a;
    asm("{ .reg .u64 t; cvta.to.shared.u64 t, %1; cvt.u32.u64 %0, t; }" : "=r"(a) : "l"(p));
    return a;
}
__device__ __forceinline__ void ldsm_x4(uint32_t a[4], uint32_t addr) {
    asm volatile("ldmatrix.sync.aligned.m8n8.x4.shared.b16 {%0,%1,%2,%3}, [%4];"
        : "=r"(a[0]), "=r"(a[1]), "=r"(a[2]), "=r"(a[3]) : "r"(addr));
}
__device__ __forceinline__ void ldsm_x4t(uint32_t a[4], uint32_t addr) {
    asm volatile("ldmatrix.sync.aligned.m8n8.x4.trans.shared.b16 {%0,%1,%2,%3}, [%4];"
        : "=r"(a[0]), "=r"(a[1]), "=r"(a[2]), "=r"(a[3]) : "r"(addr));
}
__device__ __forceinline__ void mma_bf16(float c[4], const uint32_t a[4], const uint32_t b[2]) {
    asm volatile("mma.sync.aligned.m16n8k16.row.col.f32.bf16.bf16.f32 "
        "{%0,%1,%2,%3}, {%4,%5,%6,%7}, {%8,%9}, {%0,%1,%2,%3};"
        : "+f"(c[0]), "+f"(c[1]), "+f"(c[2]), "+f"(c[3])
        : "r"(a[0]), "r"(a[1]), "r"(a[2]), "r"(a[3]), "r"(b[0]), "r"(b[1]));
}
// pack two floats -> bf16x2 (hi) and residual bf16x2 (lo)
__device__ __forceinline__ void split2(float x, float y, uint32_t& h, uint32_t& l) {
    __nv_bfloat16 hx = __float2bfloat16_rn(x), hy = __float2bfloat16_rn(y);
    __nv_bfloat162 hv = __halves2bfloat162(hx, hy);
    h = *(uint32_t*)&hv;
    __nv_bfloat162 lv = __halves2bfloat162(
        __float2bfloat16_rn(x - __bfloat162float(hx)),
        __float2bfloat16_rn(y - __bfloat162float(hy)));
    l = *(uint32_t*)&lv;
}

// ===========================================================================
// prep kernels
// ===========================================================================
__global__ void qa_kernel(const float* __restrict__ P, const float* __restrict__ w) {
    int row  = blockIdx.x * blockDim.y + threadIdx.y;
    int lane = threadIdx.x;
    if (row >= NROWS) return;
    const float* p = P + (size_t)row * Dd;
    float s = 0.f;
    #pragma unroll
    for (int k = lane; k < Dd; k += 32) s += p[k] * w[k];
    #pragma unroll
    for (int off = 16; off > 0; off >>= 1) s += __shfl_xor_sync(0xffffffffu, s, off);
    if (lane == 0) g_qa[row] = s;
}

// split w1/w2/w3 (256x128 f32, n-contiguous) into bf16x2 hi/lo pairs along n
__global__ void wsplit_kernel(const float* __restrict__ w1, const float* __restrict__ w2,
                              const float* __restrict__ w3) {
    int idx = blockIdx.x * 256 + threadIdx.x;    // 16384 u32 per weight
    if (idx >= 16384) return;
    const float* srcs[3] = { w1, w2, w3 };
    #pragma unroll
    for (int g = 0; g < 3; g++) {
        float x = srcs[g][idx * 2], y = srcs[g][idx * 2 + 1];
        uint32_t h, l;
        split2(x, y, h, l);
        g_whu[g * 16384 + idx] = h;
        g_wlu[g * 16384 + idx] = l;
    }
}

// ===========================================================================
// HMMA flash attention.
// S = (P*wc) @ P^T (+qa[j] col bias); no-max softmax; probs stay in regs
// (S frag layout == PV A frag layout); K tile doubles as V via trans ldsm.
// bf16 hi/lo 3-term split; k-tile OUTER so mma chains hit 16 distinct accs.
// ===========================================================================
#define LDT 136                              // bf16 tile stride (conflict-free)
#define FS_QH 0
#define FS_QL 34816
#define FS_KH 69632
#define FS_KL 104448
#define FS_QA 139264
#define FS_TOT (FS_QA + 512)

__global__ __launch_bounds__(256, 1)
void flash_hmma(const float* __restrict__ P, const float* __restrict__ w) {
    extern __shared__ char smem[];
    const uint32_t sb = smem_u32(smem);
    float* qas = (float*)(smem + FS_QA);
    const int tid = threadIdx.x, lane = tid & 31, wm = tid >> 5;
    const int b = blockIdx.y, i0 = blockIdx.x * 128;
    const int lg = lane >> 3, li = lane & 7;
    const int qr = lane >> 2, qc2 = (lane & 3) << 1;

    // ---- convert Q = P*wc into bf16 hi/lo tiles ----
    {
        const int r = tid >> 1, ch = (tid & 1) << 6;
        const float4* src = (const float4*)(P + ((size_t)(b * Nn + i0 + r)) * Dd + ch);
        const float4* wc4 = (const float4*)(w + 2 * Dd + ch);
        #pragma unroll
        for (int c4 = 0; c4 < 16; c4++) {
            float4 v = src[c4], wv = wc4[c4];
            int c0 = ch + c4 * 4;
            uint32_t h, l;
            split2(v.x * wv.x, v.y * wv.y, h, l);
            *(uint32_t*)(smem + FS_QH + (r * LDT + c0) * 2) = h;
            *(uint32_t*)(smem + FS_QL + (r * LDT + c0) * 2) = l;
            split2(v.z * wv.z, v.w * wv.w, h, l);
            *(uint32_t*)(smem + FS_QH + (r * LDT + c0 + 2) * 2) = h;
            *(uint32_t*)(smem + FS_QL + (r * LDT + c0 + 2) * 2) = l;
        }
    }

    float o[16][4];
    #pragma unroll
    for (int n = 0; n < 16; n++)
        #pragma unroll
        for (int u = 0; u < 4; u++) o[n][u] = 0.f;
    float lsum0 = 0.f, lsum1 = 0.f;

    for (int j0 = 0; j0 < Nn; j0 += 128) {
        __syncthreads();   // prior compute done (and Q visible on iter 0)
        // ---- convert K tile (token-major bf16 hi/lo) ----
        {
            const int r = tid >> 1, ch = (tid & 1) << 6;
            const float4* src = (const float4*)(P + ((size_t)(b * Nn + j0 + r)) * Dd + ch);
            #pragma unroll
            for (int c4 = 0; c4 < 16; c4++) {
                float4 v = src[c4];
                int c0 = ch + c4 * 4;
                uint32_t h, l;
                split2(v.x, v.y, h, l);
                *(uint32_t*)(smem + FS_KH + (r * LDT + c0) * 2) = h;
                *(uint32_t*)(smem + FS_KL + (r * LDT + c0) * 2) = l;
                split2(v.z, v.w, h, l);
                *(uint32_t*)(smem + FS_KH + (r * LDT + c0 + 2) * 2) = h;
                *(uint32_t*)(smem + FS_KL + (r * LDT + c0 + 2) * 2) = l;
            }
            if (tid < 128) qas[tid] = g_qa[(size_t)b * Nn + j0 + tid];
        }
        __syncthreads();

        // ---- S = Q @ K^T, k-tile outer, terms QhKh + QlKh + QhKl ----
        float s[16][4];
        #pragma unroll
        for (int n = 0; n < 16; n++)
            #pragma unroll
            for (int u = 0; u < 4; u++) s[n][u] = 0.f;

        #pragma unroll
        for (int kt = 0; kt < 8; kt++) {
            const int arow = wm * 16 + ((lg & 1) << 3) + li;
            const int acol = kt * 16 + ((lg >> 1) << 3);
            uint32_t ah[4], al[4];
            ldsm_x4(ah, sb + FS_QH + (arow * LDT + acol) * 2);
            ldsm_x4(al, sb + FS_QL + (arow * LDT + acol) * 2);

            const int brow = ((lg >> 1) << 3) + li;
            const int bcol = kt * 16 + ((lg & 1) << 3);
            uint32_t bh[8][4];
            #pragma unroll
            for (int jp = 0; jp < 8; jp++)
                ldsm_x4(bh[jp], sb + FS_KH + ((jp * 16 + brow) * LDT + bcol) * 2);
            #pragma unroll
            for (int jp = 0; jp < 8; jp++) {
                mma_bf16(s[2 * jp],     ah, bh[jp]);
                mma_bf16(s[2 * jp + 1], ah, bh[jp] + 2);
            }
            #pragma unroll
            for (int jp = 0; jp < 8; jp++) {
                mma_bf16(s[2 * jp],     al, bh[jp]);
                mma_bf16(s[2 * jp + 1], al, bh[jp] + 2);
            }
            #pragma unroll
            for (int jp = 0; jp < 8; jp++) {
                uint32_t bl[4];
                ldsm_x4(bl, sb + FS_KL + ((jp * 16 + brow) * LDT + bcol) * 2);
                mma_bf16(s[2 * jp],     ah, bl);
                mma_bf16(s[2 * jp + 1], ah, bl + 2);
            }
        }

        // ---- exp (+qa col bias), pack probs into PV A-fragments ----
        uint32_t ph[8][4], pl[8][4];
        #pragma unroll
        for (int jn = 0; jn < 16; jn++) {
            int cb = jn * 8 + qc2;
            float q0 = qas[cb], q1 = qas[cb + 1];
            float p0 = __expf(s[jn][0] + q0);
            float p1 = __expf(s[jn][1] + q1);
            float p2 = __expf(s[jn][2] + q0);
            float p3 = __expf(s[jn][3] + q1);
            lsum0 += p0 + p1;
            lsum1 += p2 + p3;
            int kt = jn >> 1, hv = (jn & 1) << 1;
            split2(p0, p1, ph[kt][hv],     pl[kt][hv]);
            split2(p2, p3, ph[kt][hv + 1], pl[kt][hv + 1]);
        }

        // ---- O += P @ V (V tile == K tile via trans ldsm), k-tile outer ----
        #pragma unroll
        for (int kt = 0; kt < 8; kt++) {
            const int brow = kt * 16 + ((lg & 1) << 3) + li;
            const int bcol = (lg >> 1) << 3;
            uint32_t bh[8][4];
            #pragma unroll
            for (int dp = 0; dp < 8; dp++)
                ldsm_x4t(bh[dp], sb + FS_KH + (brow * LDT + dp * 16 + bcol) * 2);
            #pragma unroll
            for (int dp = 0; dp < 8; dp++) {
                mma_bf16(o[2 * dp],     ph[kt], bh[dp]);
                mma_bf16(o[2 * dp + 1], ph[kt], bh[dp] + 2);
            }
            #pragma unroll
            for (int dp = 0; dp < 8; dp++) {
                mma_bf16(o[2 * dp],     pl[kt], bh[dp]);
                mma_bf16(o[2 * dp + 1], pl[kt], bh[dp] + 2);
            }
            #pragma unroll
            for (int dp = 0; dp < 8; dp++) {
                uint32_t bl[4];
                ldsm_x4t(bl, sb + FS_KL + (brow * LDT + dp * 16 + bcol) * 2);
                mma_bf16(o[2 * dp],     ph[kt], bl);
                mma_bf16(o[2 * dp + 1], ph[kt], bl + 2);
            }
        }
    }

    // ---- normalize, store itr ----
    lsum0 += __shfl_xor_sync(0xffffffffu, lsum0, 1);
    lsum0 += __shfl_xor_sync(0xffffffffu, lsum0, 2);
    lsum1 += __shfl_xor_sync(0xffffffffu, lsum1, 1);
    lsum1 += __shfl_xor_sync(0xffffffffu, lsum1, 2);
    float inv0 = 1.f / lsum0, inv1 = 1.f / lsum1;
    const size_t r0 = (size_t)b * Nn + i0 + wm * 16 + qr;
    #pragma unroll
    for (int dn = 0; dn < 16; dn++) {
        int c = dn * 8 + qc2;
        *(float2*)(g_itr + r0 * Dd + c)       = make_float2(o[dn][0] * inv0, o[dn][1] * inv0);
        *(float2*)(g_itr + (r0 + 8) * Dd + c) = make_float2(o[dn][2] * inv1, o[dn][3] * inv1);
    }
}

// ===========================================================================
// HMMA fused gated MLP: X=[P,itr] (64 rows/CTA, K=256), 3 weights,
// 3-term split with shared Wh fragments, k-tile outer (8 distinct accs).
// ===========================================================================
#define XLD 264
#define MS_XH 0
#define MS_XL 33792
#define MS_WH 67584
#define MS_WL 137216
#define MS_TOT 206848

__global__ __launch_bounds__(256, 1)
void mlp_hmma(const float* __restrict__ P,
              const float* __restrict__ b1, const float* __restrict__ b2,
              const float* __restrict__ b3, float* __restrict__ out) {
    extern __shared__ char smem[];
    const uint32_t sb = smem_u32(smem);
    const int tid = threadIdx.x, lane = tid & 31, wid = tid >> 5;
    const int wm = wid & 3, wn = wid >> 2;
    const int lg = lane >> 3, li = lane & 7;
    const int qr = lane >> 2, qc2 = (lane & 3) << 1;
    const int row0 = blockIdx.x * 64;

    // ---- convert X = [P | itr] into bf16 hi/lo (64 x 256) ----
    {
        const int r = tid >> 2, q = tid & 3;
        const int c0 = q * 64;
        const float* base = (q < 2)
            ? (P     + ((size_t)(row0 + r)) * Dd + q * 64)
            : (g_itr + ((size_t)(row0 + r)) * Dd + (q - 2) * 64);
        const float4* src = (const float4*)base;
        #pragma unroll
        for (int c4 = 0; c4 < 16; c4++) {
            float4 v = src[c4];
            int c = c0 + c4 * 4;
            uint32_t h, l;
            split2(v.x, v.y, h, l);
            *(uint32_t*)(smem + MS_XH + (r * XLD + c) * 2) = h;
            *(uint32_t*)(smem + MS_XL + (r * XLD + c) * 2) = l;
            split2(v.z, v.w, h, l);
            *(uint32_t*)(smem + MS_XH + (r * XLD + c + 2) * 2) = h;
            *(uint32_t*)(smem + MS_XL + (r * XLD + c + 2) * 2) = l;
        }
    }

    float acc[3][8][4];
    #pragma unroll
    for (int g = 0; g < 3; g++)
        #pragma unroll
        for (int n = 0; n < 8; n++)
            #pragma unroll
            for (int u = 0; u < 4; u++) acc[g][n][u] = 0.f;

    #pragma unroll 1
    for (int g = 0; g < 3; g++) {
        __syncthreads();   // X ready (iter 0) / prior W reads done
        // load W_g hi/lo into padded smem (256 k-rows x 128 n, u32 stride 68)
        {
            const uint32_t* wh = g_whu + g * 16384;
            const uint32_t* wl = g_wlu + g * 16384;
            uint32_t* dh = (uint32_t*)(smem + MS_WH);
            uint32_t* dl = (uint32_t*)(smem + MS_WL);
            #pragma unroll
            for (int t = 0; t < 64; t++) {
                int idx = tid + t * 256;            // 16384 u32
                int r = idx >> 6, c = idx & 63;
                dh[r * 68 + c] = wh[idx];
                dl[r * 68 + c] = wl[idx];
            }
        }
        __syncthreads();

        #pragma unroll
        for (int kt = 0; kt < 16; kt++) {
            const int arow = wm * 16 + ((lg & 1) << 3) + li;
            const int acol = kt * 16 + ((lg >> 1) << 3);
            uint32_t ah[4], al[4];
            ldsm_x4(ah, sb + MS_XH + (arow * XLD + acol) * 2);
            ldsm_x4(al, sb + MS_XL + (arow * XLD + acol) * 2);

            const int brow = kt * 16 + ((lg & 1) << 3) + li;
            const int bcol = wn * 64 + ((lg >> 1) << 3);
            uint32_t bh[4][4];
            #pragma unroll
            for (int np = 0; np < 4; np++)
                ldsm_x4t(bh[np], sb + MS_WH + (brow * 136 + np * 16 + bcol) * 2);
            #pragma unroll
            for (int np = 0; np < 4; np++) {
                mma_bf16(acc[g][2 * np],     ah, bh[np]);
                mma_bf16(acc[g][2 * np + 1], ah, bh[np] + 2);
            }
            #pragma unroll
            for (int np = 0; np < 4; np++) {
                mma_bf16(acc[g][2 * np],     al, bh[np]);
                mma_bf16(acc[g][2 * np + 1], al, bh[np] + 2);
            }
            #pragma unroll
            for (int np = 0; np < 4; np++) {
                uint32_t bl[4];
                ldsm_x4t(bl, sb + MS_WL + (brow * 136 + np * 16 + bcol) * 2);
                mma_bf16(acc[g][2 * np],     ah, bl);
                mma_bf16(acc[g][2 * np + 1], ah, bl + 2);
            }
        }
    }

    // ---- epilogue: out = sigmoid(a2+b2)*P + sigmoid(a3+b3)*tanh(a1+b1) ----
    #pragma unroll
    for (int n = 0; n < 8; n++) {
        int c = wn * 64 + n * 8 + qc2;
        float bb1x = b1[c], bb1y = b1[c + 1];
        float bb2x = b2[c], bb2y = b2[c + 1];
        float bb3x = b3[c], bb3y = b3[c + 1];
        #pragma unroll
        for (int half = 0; half < 2; half++) {
            size_t r = (size_t)row0 + wm * 16 + qr + half * 8;
            float2 pv = *(const float2*)(P + r * Dd + c);
            float a1x = acc[0][n][half * 2], a1y = acc[0][n][half * 2 + 1];
            float a2x = acc[1][n][half * 2], a2y = acc[1][n][half * 2 + 1];
            float a3x = acc[2][n][half * 2], a3y = acc[2][n][half * 2 + 1];
            float zx = tanhf(a1x + bb1x), zy = tanhf(a1y + bb1y);
            float rx = 1.f / (1.f + __expf(-(a2x + bb2x)));
            float ry = 1.f / (1.f + __expf(-(a2y + bb2y)));
            float fx = 1.f / (1.f + __expf(-(a3x + bb3x)));
            float fy = 1.f / (1.f + __expf(-(a3y + bb3y)));
            *(float2*)(out + r * Dd + c) =
                make_float2(rx * pv.x + fx * zx, ry * pv.y + fy * zy);
        }
    }
}

// ===========================================================================
extern "C" void kernel_launch(void* const* d_in, const int* in_sizes, int n_in,
                              void* d_out, int out_size) {
    const float* P  = (const float*)d_in[0];
    const float* w  = (const float*)d_in[1];
    const float* w1 = (const float*)d_in[2];
    const float* w2 = (const float*)d_in[3];
    const float* w3 = (const float*)d_in[4];
    const float* b1 = (const float*)d_in[5];
    const float* b2 = (const float*)d_in[6];
    const float* b3 = (const float*)d_in[7];
    float* out = (float*)d_out;

    cudaFuncSetAttribute(flash_hmma, cudaFuncAttributeMaxDynamicSharedMemorySize, FS_TOT);
    cudaFuncSetAttribute(mlp_hmma, cudaFuncAttributeMaxDynamicSharedMemorySize, MS_TOT);

    wsplit_kernel<<<64, 256>>>(w1, w2, w3);

    dim3 qb(32, 8);
    qa_kernel<<<NROWS / 8, qb>>>(P, w);

    dim3 fg(Nn / 128, Bsz);
    flash_hmma<<<fg, 256, FS_TOT>>>(P, w);

    mlp_hmma<<<NROWS / 64, 256, MS_TOT>>>(P, b1, b2, b3, out);
}

// round 6
// speedup vs baseline: 1.5265x; 1.5265x over previous
#include <cuda_runtime.h>
#include <cuda_bf16.h>
#include <cstdint>
#include <math.h>

#define Bsz 32
#define Nn  1024
#define Dd  128
#define NROWS (Bsz*Nn)

// Scratch (device globals: allocation-free rule)
__device__ float g_itr[NROWS * Dd];          // itr_attn fp32
__device__ float g_qa[NROWS];                // qa[j] = P[j].wa
__device__ uint32_t g_whu[3 * 16384];        // weights bf16x2 hi (3 x 256x128)
__device__ uint32_t g_wlu[3 * 16384];        // weights bf16x2 lo

// ===========================================================================
// helpers
// ===========================================================================
__device__ __forceinline__ uint32_t smem_u32(const void* p) {
    uint32_t a;
    asm("{ .reg .u64 t; cvta.to.shared.u64 t, %1; cvt.u32.u64 %0, t; }" : "=r"(a) : "l"(p));
    return a;
}
__device__ __forceinline__ void ldsm_x4(uint32_t a[4], uint32_t addr) {
    asm volatile("ldmatrix.sync.aligned.m8n8.x4.shared.b16 {%0,%1,%2,%3}, [%4];"
        : "=r"(a[0]), "=r"(a[1]), "=r"(a[2]), "=r"(a[3]) : "r"(addr));
}
__device__ __forceinline__ void ldsm_x4t(uint32_t a[4], uint32_t addr) {
    asm volatile("ldmatrix.sync.aligned.m8n8.x4.trans.shared.b16 {%0,%1,%2,%3}, [%4];"
        : "=r"(a[0]), "=r"(a[1]), "=r"(a[2]), "=r"(a[3]) : "r"(addr));
}
__device__ __forceinline__ void mma_bf16(float c[4], const uint32_t a[4], const uint32_t b[2]) {
    asm volatile("mma.sync.aligned.m16n8k16.row.col.f32.bf16.bf16.f32 "
        "{%0,%1,%2,%3}, {%4,%5,%6,%7}, {%8,%9}, {%0,%1,%2,%3};"
        : "+f"(c[0]), "+f"(c[1]), "+f"(c[2]), "+f"(c[3])
        : "r"(a[0]), "r"(a[1]), "r"(a[2]), "r"(a[3]), "r"(b[0]), "r"(b[1]));
}
// pack two floats -> bf16x2 (hi) and residual bf16x2 (lo)
__device__ __forceinline__ void split2(float x, float y, uint32_t& h, uint32_t& l) {
    __nv_bfloat16 hx = __float2bfloat16_rn(x), hy = __float2bfloat16_rn(y);
    __nv_bfloat162 hv = __halves2bfloat162(hx, hy);
    h = *(uint32_t*)&hv;
    __nv_bfloat162 lv = __halves2bfloat162(
        __float2bfloat16_rn(x - __bfloat162float(hx)),
        __float2bfloat16_rn(y - __bfloat162float(hy)));
    l = *(uint32_t*)&lv;
}

// ===========================================================================
// prep kernels
// ===========================================================================
__global__ void qa_kernel(const float* __restrict__ P, const float* __restrict__ w) {
    int row  = blockIdx.x * blockDim.y + threadIdx.y;
    int lane = threadIdx.x;
    if (row >= NROWS) return;
    const float* p = P + (size_t)row * Dd;
    float s = 0.f;
    #pragma unroll
    for (int k = lane; k < Dd; k += 32) s += p[k] * w[k];
    #pragma unroll
    for (int off = 16; off > 0; off >>= 1) s += __shfl_xor_sync(0xffffffffu, s, off);
    if (lane == 0) g_qa[row] = s;
}

// split w1/w2/w3 (256x128 f32, n-contiguous) into bf16x2 hi/lo pairs along n
__global__ void wsplit_kernel(const float* __restrict__ w1, const float* __restrict__ w2,
                              const float* __restrict__ w3) {
    int idx = blockIdx.x * 256 + threadIdx.x;    // 16384 u32 per weight
    if (idx >= 16384) return;
    const float* srcs[3] = { w1, w2, w3 };
    #pragma unroll
    for (int g = 0; g < 3; g++) {
        float x = srcs[g][idx * 2], y = srcs[g][idx * 2 + 1];
        uint32_t h, l;
        split2(x, y, h, l);
        g_whu[g * 16384 + idx] = h;
        g_wlu[g * 16384 + idx] = l;
    }
}

// ===========================================================================
// HMMA flash attention.
// S = (P*wc) @ P^T (+qa[j] col bias); no-max softmax; probs stay in regs
// (S frag layout == PV A frag layout); K tile doubles as V via trans ldsm.
// bf16 hi/lo 3-term split; k-tile OUTER so mma chains hit 16 distinct accs.
// ===========================================================================
#define LDT 136                              // bf16 tile stride (conflict-free)
#define FS_QH 0
#define FS_QL 34816
#define FS_KH 69632
#define FS_KL 104448
#define FS_QA 139264
#define FS_TOT (FS_QA + 512)

__global__ __launch_bounds__(256, 1)
void flash_hmma(const float* __restrict__ P, const float* __restrict__ w) {
    extern __shared__ char smem[];
    const uint32_t sb = smem_u32(smem);
    float* qas = (float*)(smem + FS_QA);
    const int tid = threadIdx.x, lane = tid & 31, wm = tid >> 5;
    const int b = blockIdx.y, i0 = blockIdx.x * 128;
    const int lg = lane >> 3, li = lane & 7;
    const int qr = lane >> 2, qc2 = (lane & 3) << 1;

    // ---- convert Q = P*wc into bf16 hi/lo tiles ----
    {
        const int r = tid >> 1, ch = (tid & 1) << 6;
        const float4* src = (const float4*)(P + ((size_t)(b * Nn + i0 + r)) * Dd + ch);
        const float4* wc4 = (const float4*)(w + 2 * Dd + ch);
        #pragma unroll
        for (int c4 = 0; c4 < 16; c4++) {
            float4 v = src[c4], wv = wc4[c4];
            int c0 = ch + c4 * 4;
            uint32_t h, l;
            split2(v.x * wv.x, v.y * wv.y, h, l);
            *(uint32_t*)(smem + FS_QH + (r * LDT + c0) * 2) = h;
            *(uint32_t*)(smem + FS_QL + (r * LDT + c0) * 2) = l;
            split2(v.z * wv.z, v.w * wv.w, h, l);
            *(uint32_t*)(smem + FS_QH + (r * LDT + c0 + 2) * 2) = h;
            *(uint32_t*)(smem + FS_QL + (r * LDT + c0 + 2) * 2) = l;
        }
    }

    float o[16][4];
    #pragma unroll
    for (int n = 0; n < 16; n++)
        #pragma unroll
        for (int u = 0; u < 4; u++) o[n][u] = 0.f;
    float lsum0 = 0.f, lsum1 = 0.f;

    for (int j0 = 0; j0 < Nn; j0 += 128) {
        __syncthreads();   // prior compute done (and Q visible on iter 0)
        // ---- convert K tile (token-major bf16 hi/lo) ----
        {
            const int r = tid >> 1, ch = (tid & 1) << 6;
            const float4* src = (const float4*)(P + ((size_t)(b * Nn + j0 + r)) * Dd + ch);
            #pragma unroll
            for (int c4 = 0; c4 < 16; c4++) {
                float4 v = src[c4];
                int c0 = ch + c4 * 4;
                uint32_t h, l;
                split2(v.x, v.y, h, l);
                *(uint32_t*)(smem + FS_KH + (r * LDT + c0) * 2) = h;
                *(uint32_t*)(smem + FS_KL + (r * LDT + c0) * 2) = l;
                split2(v.z, v.w, h, l);
                *(uint32_t*)(smem + FS_KH + (r * LDT + c0 + 2) * 2) = h;
                *(uint32_t*)(smem + FS_KL + (r * LDT + c0 + 2) * 2) = l;
            }
            if (tid < 128) qas[tid] = g_qa[(size_t)b * Nn + j0 + tid];
        }
        __syncthreads();

        // ---- S = Q @ K^T, k-tile outer, terms QhKh + QlKh + QhKl ----
        float s[16][4];
        #pragma unroll
        for (int n = 0; n < 16; n++)
            #pragma unroll
            for (int u = 0; u < 4; u++) s[n][u] = 0.f;

        #pragma unroll
        for (int kt = 0; kt < 8; kt++) {
            const int arow = wm * 16 + ((lg & 1) << 3) + li;
            const int acol = kt * 16 + ((lg >> 1) << 3);
            uint32_t ah[4], al[4];
            ldsm_x4(ah, sb + FS_QH + (arow * LDT + acol) * 2);
            ldsm_x4(al, sb + FS_QL + (arow * LDT + acol) * 2);

            const int brow = ((lg >> 1) << 3) + li;
            const int bcol = kt * 16 + ((lg & 1) << 3);
            uint32_t bh[8][4];
            #pragma unroll
            for (int jp = 0; jp < 8; jp++)
                ldsm_x4(bh[jp], sb + FS_KH + ((jp * 16 + brow) * LDT + bcol) * 2);
            #pragma unroll
            for (int jp = 0; jp < 8; jp++) {
                mma_bf16(s[2 * jp],     ah, bh[jp]);
                mma_bf16(s[2 * jp + 1], ah, bh[jp] + 2);
            }
            #pragma unroll
            for (int jp = 0; jp < 8; jp++) {
                mma_bf16(s[2 * jp],     al, bh[jp]);
                mma_bf16(s[2 * jp + 1], al, bh[jp] + 2);
            }
            #pragma unroll
            for (int jp = 0; jp < 8; jp++) {
                uint32_t bl[4];
                ldsm_x4(bl, sb + FS_KL + ((jp * 16 + brow) * LDT + bcol) * 2);
                mma_bf16(s[2 * jp],     ah, bl);
                mma_bf16(s[2 * jp + 1], ah, bl + 2);
            }
        }

        // ---- exp (+qa col bias), pack probs into PV A-fragments ----
        uint32_t ph[8][4], pl[8][4];
        #pragma unroll
        for (int jn = 0; jn < 16; jn++) {
            int cb = jn * 8 + qc2;
            float q0 = qas[cb], q1 = qas[cb + 1];
            float p0 = __expf(s[jn][0] + q0);
            float p1 = __expf(s[jn][1] + q1);
            float p2 = __expf(s[jn][2] + q0);
            float p3 = __expf(s[jn][3] + q1);
            lsum0 += p0 + p1;
            lsum1 += p2 + p3;
            int kt = jn >> 1, hv = (jn & 1) << 1;
            split2(p0, p1, ph[kt][hv],     pl[kt][hv]);
            split2(p2, p3, ph[kt][hv + 1], pl[kt][hv + 1]);
        }

        // ---- O += P @ V (V tile == K tile via trans ldsm), k-tile outer ----
        #pragma unroll
        for (int kt = 0; kt < 8; kt++) {
            const int brow = kt * 16 + ((lg & 1) << 3) + li;
            const int bcol = (lg >> 1) << 3;
            uint32_t bh[8][4];
            #pragma unroll
            for (int dp = 0; dp < 8; dp++)
                ldsm_x4t(bh[dp], sb + FS_KH + (brow * LDT + dp * 16 + bcol) * 2);
            #pragma unroll
            for (int dp = 0; dp < 8; dp++) {
                mma_bf16(o[2 * dp],     ph[kt], bh[dp]);
                mma_bf16(o[2 * dp + 1], ph[kt], bh[dp] + 2);
            }
            #pragma unroll
            for (int dp = 0; dp < 8; dp++) {
                mma_bf16(o[2 * dp],     pl[kt], bh[dp]);
                mma_bf16(o[2 * dp + 1], pl[kt], bh[dp] + 2);
            }
            #pragma unroll
            for (int dp = 0; dp < 8; dp++) {
                uint32_t bl[4];
                ldsm_x4t(bl, sb + FS_KL + (brow * LDT + dp * 16 + bcol) * 2);
                mma_bf16(o[2 * dp],     ph[kt], bl);
                mma_bf16(o[2 * dp + 1], ph[kt], bl + 2);
            }
        }
    }

    // ---- normalize, store itr ----
    lsum0 += __shfl_xor_sync(0xffffffffu, lsum0, 1);
    lsum0 += __shfl_xor_sync(0xffffffffu, lsum0, 2);
    lsum1 += __shfl_xor_sync(0xffffffffu, lsum1, 1);
    lsum1 += __shfl_xor_sync(0xffffffffu, lsum1, 2);
    float inv0 = 1.f / lsum0, inv1 = 1.f / lsum1;
    const size_t r0 = (size_t)b * Nn + i0 + wm * 16 + qr;
    #pragma unroll
    for (int dn = 0; dn < 16; dn++) {
        int c = dn * 8 + qc2;
        *(float2*)(g_itr + r0 * Dd + c)       = make_float2(o[dn][0] * inv0, o[dn][1] * inv0);
        *(float2*)(g_itr + (r0 + 8) * Dd + c) = make_float2(o[dn][2] * inv1, o[dn][3] * inv1);
    }
}

// ===========================================================================
// HMMA fused gated MLP: X=[P,itr] (64 rows/CTA, K=256), 3 weights,
// 3-term split with shared Wh fragments, k-tile outer (8 distinct accs).
// ===========================================================================
#define XLD 264
#define MS_XH 0
#define MS_XL 33792
#define MS_WH 67584
#define MS_WL 137216
#define MS_TOT 206848

__global__ __launch_bounds__(256, 1)
void mlp_hmma(const float* __restrict__ P,
              const float* __restrict__ b1, const float* __restrict__ b2,
              const float* __restrict__ b3, float* __restrict__ out) {
    extern __shared__ char smem[];
    const uint32_t sb = smem_u32(smem);
    const int tid = threadIdx.x, lane = tid & 31, wid = tid >> 5;
    const int wm = wid & 3, wn = wid >> 2;
    const int lg = lane >> 3, li = lane & 7;
    const int qr = lane >> 2, qc2 = (lane & 3) << 1;
    const int row0 = blockIdx.x * 64;

    // ---- convert X = [P | itr] into bf16 hi/lo (64 x 256) ----
    {
        const int r = tid >> 2, q = tid & 3;
        const int c0 = q * 64;
        const float* base = (q < 2)
            ? (P     + ((size_t)(row0 + r)) * Dd + q * 64)
            : (g_itr + ((size_t)(row0 + r)) * Dd + (q - 2) * 64);
        const float4* src = (const float4*)base;
        #pragma unroll
        for (int c4 = 0; c4 < 16; c4++) {
            float4 v = src[c4];
            int c = c0 + c4 * 4;
            uint32_t h, l;
            split2(v.x, v.y, h, l);
            *(uint32_t*)(smem + MS_XH + (r * XLD + c) * 2) = h;
            *(uint32_t*)(smem + MS_XL + (r * XLD + c) * 2) = l;
            split2(v.z, v.w, h, l);
            *(uint32_t*)(smem + MS_XH + (r * XLD + c + 2) * 2) = h;
            *(uint32_t*)(smem + MS_XL + (r * XLD + c + 2) * 2) = l;
        }
    }

    float acc[3][8][4];
    #pragma unroll
    for (int g = 0; g < 3; g++)
        #pragma unroll
        for (int n = 0; n < 8; n++)
            #pragma unroll
            for (int u = 0; u < 4; u++) acc[g][n][u] = 0.f;

    #pragma unroll 1
    for (int g = 0; g < 3; g++) {
        __syncthreads();   // X ready (iter 0) / prior W reads done
        // load W_g hi/lo into padded smem (256 k-rows x 128 n, u32 stride 68)
        {
            const uint32_t* wh = g_whu + g * 16384;
            const uint32_t* wl = g_wlu + g * 16384;
            uint32_t* dh = (uint32_t*)(smem + MS_WH);
            uint32_t* dl = (uint32_t*)(smem + MS_WL);
            #pragma unroll
            for (int t = 0; t < 64; t++) {
                int idx = tid + t * 256;            // 16384 u32
                int r = idx >> 6, c = idx & 63;
                dh[r * 68 + c] = wh[idx];
                dl[r * 68 + c] = wl[idx];
            }
        }
        __syncthreads();

        #pragma unroll
        for (int kt = 0; kt < 16; kt++) {
            const int arow = wm * 16 + ((lg & 1) << 3) + li;
            const int acol = kt * 16 + ((lg >> 1) << 3);
            uint32_t ah[4], al[4];
            ldsm_x4(ah, sb + MS_XH + (arow * XLD + acol) * 2);
            ldsm_x4(al, sb + MS_XL + (arow * XLD + acol) * 2);

            const int brow = kt * 16 + ((lg & 1) << 3) + li;
            const int bcol = wn * 64 + ((lg >> 1) << 3);
            uint32_t bh[4][4];
            #pragma unroll
            for (int np = 0; np < 4; np++)
                ldsm_x4t(bh[np], sb + MS_WH + (brow * 136 + np * 16 + bcol) * 2);
            #pragma unroll
            for (int np = 0; np < 4; np++) {
                mma_bf16(acc[g][2 * np],     ah, bh[np]);
                mma_bf16(acc[g][2 * np + 1], ah, bh[np] + 2);
            }
            #pragma unroll
            for (int np = 0; np < 4; np++) {
                mma_bf16(acc[g][2 * np],     al, bh[np]);
                mma_bf16(acc[g][2 * np + 1], al, bh[np] + 2);
            }
            #pragma unroll
            for (int np = 0; np < 4; np++) {
                uint32_t bl[4];
                ldsm_x4t(bl, sb + MS_WL + (brow * 136 + np * 16 + bcol) * 2);
                mma_bf16(acc[g][2 * np],     ah, bl);
                mma_bf16(acc[g][2 * np + 1], ah, bl + 2);
            }
        }
    }

    // ---- epilogue: out = sigmoid(a2+b2)*P + sigmoid(a3+b3)*tanh(a1+b1) ----
    #pragma unroll
    for (int n = 0; n < 8; n++) {
        int c = wn * 64 + n * 8 + qc2;
        float bb1x = b1[c], bb1y = b1[c + 1];
        float bb2x = b2[c], bb2y = b2[c + 1];
        float bb3x = b3[c], bb3y = b3[c + 1];
        #pragma unroll
        for (int half = 0; half < 2; half++) {
            size_t r = (size_t)row0 + wm * 16 + qr + half * 8;
            float2 pv = *(const float2*)(P + r * Dd + c);
            float a1x = acc[0][n][half * 2], a1y = acc[0][n][half * 2 + 1];
            float a2x = acc[1][n][half * 2], a2y = acc[1][n][half * 2 + 1];
            float a3x = acc[2][n][half * 2], a3y = acc[2][n][half * 2 + 1];
            float zx = tanhf(a1x + bb1x), zy = tanhf(a1y + bb1y);
            float rx = 1.f / (1.f + __expf(-(a2x + bb2x)));
            float ry = 1.f / (1.f + __expf(-(a2y + bb2y)));
            float fx = 1.f / (1.f + __expf(-(a3x + bb3x)));
            float fy = 1.f / (1.f + __expf(-(a3y + bb3y)));
            *(float2*)(out + r * Dd + c) =
                make_float2(rx * pv.x + fx * zx, ry * pv.y + fy * zy);
        }
    }
}

// ===========================================================================
extern "C" void kernel_launch(void* const* d_in, const int* in_sizes, int n_in,
                              void* d_out, int out_size) {
    const float* P  = (const float*)d_in[0];
    const float* w  = (const float*)d_in[1];
    const float* w1 = (const float*)d_in[2];
    const float* w2 = (const float*)d_in[3];
    const float* w3 = (const float*)d_in[4];
    const float* b1 = (const float*)d_in[5];
    const float* b2 = (const float*)d_in[6];
    const float* b3 = (const float*)d_in[7];
    float* out = (float*)d_out;

    cudaFuncSetAttribute(flash_hmma, cudaFuncAttributeMaxDynamicSharedMemorySize, FS_TOT);
    cudaFuncSetAttribute(mlp_hmma, cudaFuncAttributeMaxDynamicSharedMemorySize, MS_TOT);

    wsplit_kernel<<<64, 256>>>(w1, w2, w3);

    dim3 qb(32, 8);
    qa_kernel<<<NROWS / 8, qb>>>(P, w);

    dim3 fg(Nn / 128, Bsz);
    flash_hmma<<<fg, 256, FS_TOT>>>(P, w);

    mlp_hmma<<<NROWS / 64, 256, MS_TOT>>>(P, b1, b2, b3, out);
}